// round 7
// baseline (speedup 1.0000x reference)
#include <cuda_runtime.h>
#include <cuda_bf16.h>
#include <cstdint>

// Problem constants
#define NB  4        // batch
#define NN  4096     // sequence (64*64)
#define NC  128      // channels
#define ND  16       // qk head dim

__device__ __forceinline__ uint32_t smem_u32(const void* p) {
    uint32_t a;
    asm("{ .reg .u64 tmp; cvta.to.shared.u64 tmp, %1; cvt.u32.u64 %0, tmp; }"
        : "=r"(a) : "l"(p));
    return a;
}

// ---- warp MMA primitives (plain PTX, valid on sm_100 non-a) ----
__device__ __forceinline__ void mma16816(float* c, const uint32_t* a,
                                         uint32_t b0, uint32_t b1) {
    asm volatile(
        "mma.sync.aligned.m16n8k16.row.col.f32.bf16.bf16.f32 "
        "{%0,%1,%2,%3}, {%4,%5,%6,%7}, {%8,%9}, {%0,%1,%2,%3};"
        : "+f"(c[0]), "+f"(c[1]), "+f"(c[2]), "+f"(c[3])
        : "r"(a[0]), "r"(a[1]), "r"(a[2]), "r"(a[3]), "r"(b0), "r"(b1));
}
#define LDSM_X4(r0,r1,r2,r3,addr) \
    asm volatile("ldmatrix.sync.aligned.m8n8.x4.shared.b16 {%0,%1,%2,%3}, [%4];" \
        : "=r"(r0), "=r"(r1), "=r"(r2), "=r"(r3) : "r"(addr))
#define LDSM_X4_T(r0,r1,r2,r3,addr) \
    asm volatile("ldmatrix.sync.aligned.m8n8.x4.trans.shared.b16 {%0,%1,%2,%3}, [%4];" \
        : "=r"(r0), "=r"(r1), "=r"(r2), "=r"(r3) : "r"(addr))

#define CP_ASYNC16(dst, src) \
    asm volatile("cp.async.cg.shared.global [%0], [%1], 16;" :: "r"(dst), "l"(src) : "memory")
#define CP_COMMIT() asm volatile("cp.async.commit_group;" ::: "memory")
#define CP_WAIT1()  asm volatile("cp.async.wait_group 1;" ::: "memory")

// =====================================================================
// Device scratch
// =====================================================================
__device__ __nv_bfloat16 g_Qb[NB * NN * ND];            // queries = x @ Wk (bf16)
__device__ __nv_bfloat16 g_Kb[NB * NN * ND];            // keys    = x @ Wq (bf16)
__device__ __nv_bfloat16 g_V [(size_t)NB * NN * NC];    // values  = x @ Wv (bf16) [b][n][c]

// =====================================================================
// Projection GEMM (HMMA): [16384 x 128] x [128 x 160] -> V | Kb | Qb
// (unchanged from round 6 — measured ~1us)
// =====================================================================
#define PJP 272
#define WP  336
#define PSM_X 0
#define PSM_W (128 * PJP)
#define PROJ_SMEM_BYTES (PSM_W + 128 * WP)      // 77824

__global__ __launch_bounds__(256, 1) void proj_mma_kernel(
        const float* __restrict__ x,
        const float* __restrict__ Wq,
        const float* __restrict__ Wk,
        const float* __restrict__ Wv) {
    extern __shared__ char smem[];
    const uint32_t sb = smem_u32(smem);
    const int t = threadIdx.x;
    const int w = t >> 5, lane = t & 31;
    const int row0 = blockIdx.x * 128;

    {
        const float4* wv4 = (const float4*)Wv;
        #pragma unroll
        for (int i = 0; i < 16; i++) {
            int idx = t + i * 256;
            int c = idx >> 5, e4 = idx & 31;
            float4 v = wv4[idx];
            uint2 p;
            asm("cvt.rn.bf16x2.f32 %0, %1, %2;" : "=r"(p.x) : "f"(v.y), "f"(v.x));
            asm("cvt.rn.bf16x2.f32 %0, %1, %2;" : "=r"(p.y) : "f"(v.w), "f"(v.z));
            *(uint2*)(smem + PSM_W + c * WP + e4 * 8) = p;
        }
        const float4* wq4 = (const float4*)Wq;
        const float4* wk4 = (const float4*)Wk;
        #pragma unroll
        for (int i = 0; i < 2; i++) {
            int idx = t + i * 256;
            int c = idx >> 2, d4 = idx & 3;
            float4 q = wq4[idx];
            uint2 p;
            asm("cvt.rn.bf16x2.f32 %0, %1, %2;" : "=r"(p.x) : "f"(q.y), "f"(q.x));
            asm("cvt.rn.bf16x2.f32 %0, %1, %2;" : "=r"(p.y) : "f"(q.w), "f"(q.z));
            *(uint2*)(smem + PSM_W + c * WP + 256 + d4 * 8) = p;
            float4 k = wk4[idx];
            asm("cvt.rn.bf16x2.f32 %0, %1, %2;" : "=r"(p.x) : "f"(k.y), "f"(k.x));
            asm("cvt.rn.bf16x2.f32 %0, %1, %2;" : "=r"(p.y) : "f"(k.w), "f"(k.z));
            *(uint2*)(smem + PSM_W + c * WP + 288 + d4 * 8) = p;
        }
    }
    {
        const float4* src = (const float4*)(x + (size_t)row0 * NC);
        #pragma unroll
        for (int i = 0; i < 16; i++) {
            int idx = t + i * 256;
            int r = idx >> 5, ch = idx & 31;
            float4 v = src[idx];
            uint2 p;
            asm("cvt.rn.bf16x2.f32 %0, %1, %2;" : "=r"(p.x) : "f"(v.y), "f"(v.x));
            asm("cvt.rn.bf16x2.f32 %0, %1, %2;" : "=r"(p.y) : "f"(v.w), "f"(v.z));
            *(uint2*)(smem + PSM_X + r * PJP + ch * 8) = p;
        }
    }
    __syncthreads();

    float C[20][4];
    #pragma unroll
    for (int i = 0; i < 20; i++)
        #pragma unroll
        for (int j = 0; j < 4; j++) C[i][j] = 0.f;

    const uint32_t a_base = sb + PSM_X + (uint32_t)(w * 16 + (lane & 15)) * PJP
                          + (uint32_t)((lane >> 4) * 16);
    const uint32_t b_base = sb + PSM_W
                          + (uint32_t)((lane & 7) + ((lane & 8) ? 8 : 0)) * WP
                          + (uint32_t)((lane & 16) ? 16 : 0);

    #pragma unroll
    for (int k = 0; k < 8; k++) {
        uint32_t a[4];
        LDSM_X4(a[0], a[1], a[2], a[3], a_base + (uint32_t)k * 32);
        #pragma unroll
        for (int np = 0; np < 10; np++) {
            uint32_t b0, b1, b2, b3;
            LDSM_X4_T(b0, b1, b2, b3,
                      b_base + (uint32_t)k * (16 * WP) + (uint32_t)np * 32);
            mma16816(C[2*np],     a, b0, b1);
            mma16816(C[2*np + 1], a, b2, b3);
        }
    }

    const int r0 = row0 + w * 16 + (lane >> 2);
    const int r1 = r0 + 8;
    #pragma unroll
    for (int nt = 0; nt < 20; nt++) {
        const int c = nt * 8 + 2 * (lane & 3);
        uint32_t p0, p1;
        asm("cvt.rn.bf16x2.f32 %0, %1, %2;" : "=r"(p0) : "f"(C[nt][1]), "f"(C[nt][0]));
        asm("cvt.rn.bf16x2.f32 %0, %1, %2;" : "=r"(p1) : "f"(C[nt][3]), "f"(C[nt][2]));
        if (c < 128) {
            *(uint32_t*)(g_V + (size_t)r0 * NC + c) = p0;
            *(uint32_t*)(g_V + (size_t)r1 * NC + c) = p1;
        } else if (c < 144) {
            const int d = c - 128;
            *(uint32_t*)(g_Kb + (size_t)r0 * ND + d) = p0;
            *(uint32_t*)(g_Kb + (size_t)r1 * ND + d) = p1;
        } else {
            const int d = c - 144;
            *(uint32_t*)(g_Qb + (size_t)r0 * ND + d) = p0;
            *(uint32_t*)(g_Qb + (size_t)r1 * ND + d) = p1;
        }
    }
}

// =====================================================================
// Flash attention (HMMA), 4x2 warp tiling:
//   warp = (mg = w&3 -> query rows mg*32..+31, ch = w>>2 -> c cols ch*64..+63)
// V fragments loaded only for the warp's 64-col half (-50% LDSM traffic).
// QK + exp duplicated across the ch pair (cheap pipes). Keys processed in
// two 64-key halves to bound S register pressure.
// =====================================================================
#define QKP 48                         // Q/K smem row pitch (bytes)
#define VP  272                        // V smem row pitch (bytes)
#define SM_Q  0
#define SM_K0 6144
#define SM_V0 18432
#define K_BUF_BYTES 6144
#define V_BUF_BYTES 34816
#define ATTN_SMEM_BYTES (SM_V0 + 2*V_BUF_BYTES)   // 88064

__global__ __launch_bounds__(256, 1) void attn_mma_kernel(
        const float* __restrict__ x,
        const float* __restrict__ gammap,
        float* __restrict__ out) {
    extern __shared__ char smem[];
    const uint32_t sb = smem_u32(smem);
    const int t = threadIdx.x;
    const int w = t >> 5, lane = t & 31;
    const int mg = w & 3;              // query-row group (32 rows)
    const int ch = w >> 2;             // c-column half (64 cols)
    const int b = blockIdx.y;
    const int m0 = blockIdx.x * 128;

    const __nv_bfloat16* qbase = g_Qb + (size_t)b * NN * ND;
    const __nv_bfloat16* kbase = g_Kb + (size_t)b * NN * ND;
    const __nv_bfloat16* vbase = g_V  + (size_t)b * NN * NC;

    // ---- stage Q tile [128 x 16] (pitch 48B) ----
    {
        int r = t >> 1, c2 = t & 1;
        const uint4* src = (const uint4*)(qbase + (size_t)(m0 + r) * ND) + c2;
        *(uint4*)(smem + SM_Q + r * QKP + c2 * 16) = *src;
    }

    // ---- prefetch tile 0 (K+V) into buffer 0 ----
    {
        int r = t >> 1, c2 = t & 1;
        CP_ASYNC16(sb + SM_K0 + r * QKP + c2 * 16,
                   (const char*)(kbase) + (size_t)r * 32 + c2 * 16);
        #pragma unroll
        for (int i = 0; i < 8; i++) {
            int idx = t + i * 256;
            int row = idx >> 4, vch = idx & 15;
            CP_ASYNC16(sb + SM_V0 + row * VP + vch * 16,
                       (const char*)(vbase) + (size_t)row * 256 + vch * 16);
        }
    }
    CP_COMMIT();
    __syncthreads();

    // ---- Q A-fragments: 2 per warp (rows mg*32 .. mg*32+31) ----
    uint32_t qa[2][4];
    {
        uint32_t addr = sb + SM_Q + (uint32_t)(mg * 32 + (lane & 15)) * QKP
                      + (uint32_t)((lane >> 4) * 16);
        LDSM_X4(qa[0][0], qa[0][1], qa[0][2], qa[0][3], addr);
        LDSM_X4(qa[1][0], qa[1][1], qa[1][2], qa[1][3], addr + 16 * QKP);
    }

    // per-lane ldmatrix fragment base offsets
    const uint32_t kfrag = (uint32_t)((lane & 7) + ((lane & 16) ? 8 : 0)) * QKP
                         + (uint32_t)((lane & 8) ? 16 : 0);
    const uint32_t vfrag = (uint32_t)((lane & 7) + ((lane & 8) ? 8 : 0)) * VP
                         + (uint32_t)((lane & 16) ? 16 : 0)
                         + (uint32_t)(ch * 128);           // c-half select

    float O[2][8][4];
    #pragma unroll
    for (int mt = 0; mt < 2; mt++)
        #pragma unroll
        for (int i = 0; i < 8; i++)
            #pragma unroll
            for (int j = 0; j < 4; j++) O[mt][i][j] = 0.f;
    float lsum[2][2] = {{0.f, 0.f}, {0.f, 0.f}};

    for (int tile = 0; tile < 32; ++tile) {
        // prefetch next tile into the other buffer
        if (tile < 31) {
            const int nb_ = (tile + 1) & 1;
            const size_t n0n = (size_t)(tile + 1) * 128;
            int r = t >> 1, c2 = t & 1;
            CP_ASYNC16(sb + SM_K0 + nb_ * K_BUF_BYTES + r * QKP + c2 * 16,
                       (const char*)(kbase) + (n0n + r) * 32 + c2 * 16);
            #pragma unroll
            for (int i = 0; i < 8; i++) {
                int idx = t + i * 256;
                int row = idx >> 4, vch = idx & 15;
                CP_ASYNC16(sb + SM_V0 + nb_ * V_BUF_BYTES + row * VP + vch * 16,
                           (const char*)(vbase) + (n0n + row) * 256 + vch * 16);
            }
        }
        CP_COMMIT();
        CP_WAIT1();
        __syncthreads();

        const uint32_t kbuf = sb + SM_K0 + (tile & 1) * K_BUF_BYTES;
        const uint32_t vbuf = sb + SM_V0 + (tile & 1) * V_BUF_BYTES;

        // ---- process keys in two 64-key halves ----
        #pragma unroll
        for (int h = 0; h < 2; h++) {
            // S-half = Q . K^T : 2 m-tiles x 8 n8 (64 keys)
            float S[2][8][4];
            #pragma unroll
            for (int mt = 0; mt < 2; mt++)
                #pragma unroll
                for (int i = 0; i < 8; i++)
                    #pragma unroll
                    for (int j = 0; j < 4; j++) S[mt][i][j] = 0.f;
            #pragma unroll
            for (int ntp = 0; ntp < 4; ntp++) {
                uint32_t kb0, kb1, kb2, kb3;
                LDSM_X4(kb0, kb1, kb2, kb3,
                        kbuf + kfrag + (uint32_t)(h * 4 + ntp) * (16 * QKP));
                #pragma unroll
                for (int mt = 0; mt < 2; mt++) {
                    mma16816(S[mt][2*ntp],     qa[mt], kb0, kb1);
                    mma16816(S[mt][2*ntp + 1], qa[mt], kb2, kb3);
                }
            }

            // exp + pack into P A-fragments
            uint32_t pa[2][4][4];
            #pragma unroll
            for (int mt = 0; mt < 2; mt++) {
                #pragma unroll
                for (int kk = 0; kk < 4; kk++) {
                    float e0 = __expf(S[mt][2*kk][0]),   e1 = __expf(S[mt][2*kk][1]);
                    float e2 = __expf(S[mt][2*kk][2]),   e3 = __expf(S[mt][2*kk][3]);
                    float e4 = __expf(S[mt][2*kk+1][0]), e5 = __expf(S[mt][2*kk+1][1]);
                    float e6 = __expf(S[mt][2*kk+1][2]), e7 = __expf(S[mt][2*kk+1][3]);
                    lsum[mt][0] += e0 + e1 + e4 + e5;
                    lsum[mt][1] += e2 + e3 + e6 + e7;
                    asm("cvt.rn.bf16x2.f32 %0, %1, %2;" : "=r"(pa[mt][kk][0]) : "f"(e1), "f"(e0));
                    asm("cvt.rn.bf16x2.f32 %0, %1, %2;" : "=r"(pa[mt][kk][1]) : "f"(e3), "f"(e2));
                    asm("cvt.rn.bf16x2.f32 %0, %1, %2;" : "=r"(pa[mt][kk][2]) : "f"(e5), "f"(e4));
                    asm("cvt.rn.bf16x2.f32 %0, %1, %2;" : "=r"(pa[mt][kk][3]) : "f"(e7), "f"(e6));
                }
            }

            // O += P . V  (warp's 64-col half only)
            #pragma unroll
            for (int kk = 0; kk < 4; kk++) {
                #pragma unroll
                for (int cp = 0; cp < 4; cp++) {
                    uint32_t vb0, vb1, vb2, vb3;
                    LDSM_X4_T(vb0, vb1, vb2, vb3,
                              vbuf + vfrag + (uint32_t)(h * 4 + kk) * (16 * VP)
                                   + (uint32_t)cp * 32);
                    #pragma unroll
                    for (int mt = 0; mt < 2; mt++) {
                        mma16816(O[mt][2*cp],     pa[mt][kk], vb0, vb1);
                        mma16816(O[mt][2*cp + 1], pa[mt][kk], vb2, vb3);
                    }
                }
            }
        }
        __syncthreads();
    }

    // ---- softmax denominators: reduce across the 4-lane quad ----
    float inv[2][2];
    #pragma unroll
    for (int mt = 0; mt < 2; mt++)
        #pragma unroll
        for (int j = 0; j < 2; j++) {
            float s = lsum[mt][j];
            s += __shfl_xor_sync(0xffffffffu, s, 1);
            s += __shfl_xor_sync(0xffffffffu, s, 2);
            inv[mt][j] = 1.0f / s;
        }
    const float gamma = *gammap;

    // ---- write out[b, c*4096 + m] = gamma*O/lsum + x ----
    const size_t bbase = (size_t)b * (NN * NC);
    #pragma unroll
    for (int mt = 0; mt < 2; mt++) {
        const int r0 = m0 + mg * 32 + mt * 16 + (lane >> 2);
        const int r1 = r0 + 8;
        #pragma unroll
        for (int nt = 0; nt < 8; nt++) {
            const int c = ch * 64 + nt * 8 + 2 * (lane & 3);
            const size_t i00 = bbase + (size_t)c * NN + r0;
            out[i00]      = gamma * (O[mt][nt][0] * inv[mt][0]) + x[i00];
            out[i00 + NN] = gamma * (O[mt][nt][1] * inv[mt][0]) + x[i00 + NN];
            const size_t i10 = bbase + (size_t)c * NN + r1;
            out[i10]      = gamma * (O[mt][nt][2] * inv[mt][1]) + x[i10];
            out[i10 + NN] = gamma * (O[mt][nt][3] * inv[mt][1]) + x[i10 + NN];
        }
    }
}

// =====================================================================
extern "C" void kernel_launch(void* const* d_in, const int* in_sizes, int n_in,
                              void* d_out, int out_size) {
    (void)in_sizes; (void)n_in; (void)out_size;
    const float* x     = (const float*)d_in[0];
    const float* Wq    = (const float*)d_in[1];
    const float* Wk    = (const float*)d_in[2];
    const float* Wv    = (const float*)d_in[3];
    const float* gamma = (const float*)d_in[4];
    float* out = (float*)d_out;

    cudaFuncSetAttribute((const void*)proj_mma_kernel,
                         cudaFuncAttributeMaxDynamicSharedMemorySize, PROJ_SMEM_BYTES);
    cudaFuncSetAttribute((const void*)attn_mma_kernel,
                         cudaFuncAttributeMaxDynamicSharedMemorySize, ATTN_SMEM_BYTES);

    proj_mma_kernel<<<128, 256, PROJ_SMEM_BYTES>>>(x, Wq, Wk, Wv);
    attn_mma_kernel<<<dim3(32, 4), 256, ATTN_SMEM_BYTES>>>(x, gamma, out);
}